// round 16
// baseline (speedup 1.0000x reference)
#include <cuda_runtime.h>
#include <cuda_fp16.h>
#include <cstdint>
#include <math.h>

// Problem constants
#define DMODEL 1024
#define TLEN   2048
#define BATCH  4
#define NHEAD  16
#define HDIM   64
#define MTOT   (BATCH*TLEN)      // 8192

#define QSCALE (0.125f * 1.44269504089f)   // 1/sqrt(64) * log2(e), folded into q

// ---------------------------------------------------------------------------
// Global scratch, all fp16 stored as uint32 half2-words.
// ---------------------------------------------------------------------------
__device__ uint32_t g_qw  [4194304];   // flash A-frag order
__device__ uint32_t g_kw  [4194304];   // flash B-frag order
__device__ uint32_t g_vt  [4194304];   // flash B-frag order (per 64-row window)
__device__ uint32_t g_aow [4194304];   // GEMM A-frag order
__device__ uint32_t g_xrw [4194304];   // GEMM A-frag order
__device__ uint32_t g_wqkvw[1572864];  // GEMM B-frag order
__device__ uint32_t g_woutw[524288];

// ---------------------------------------------------------------------------
// Helpers
// ---------------------------------------------------------------------------
__device__ __forceinline__ uint32_t smem_u32(const void* p) {
    uint32_t a;
    asm("{ .reg .u64 t; cvta.to.shared.u64 t, %1; cvt.u32.u64 %0, t; }"
        : "=r"(a) : "l"(p));
    return a;
}

__device__ __forceinline__ uint32_t f2h2(float lo, float hi) {
    __half2 h = __floats2half2_rn(lo, hi);
    return *reinterpret_cast<uint32_t*>(&h);
}

__device__ __forceinline__ uint32_t h2exp2(float a, float b) {
    uint32_t h = f2h2(a, b), r;
    asm("ex2.approx.f16x2 %0, %1;" : "=r"(r) : "r"(h));
    return r;
}

__device__ __forceinline__ void cp16(uint32_t dst, const void* src) {
    asm volatile("cp.async.cg.shared.global [%0], [%1], 16;"
                 :: "r"(dst), "l"(src) : "memory");
}
#define CP_COMMIT() asm volatile("cp.async.commit_group;" ::: "memory")
#define CP_WAIT1()  asm volatile("cp.async.wait_group 1;" ::: "memory")
#define CP_WAIT0()  asm volatile("cp.async.wait_group 0;" ::: "memory")

// m16n8k16 row.col fp16 MMA, fp32 accumulate
__device__ __forceinline__ void mma_f16(float* c, const uint32_t* a,
                                        uint32_t b0, uint32_t b1) {
    asm volatile(
        "mma.sync.aligned.m16n8k16.row.col.f32.f16.f16.f32 "
        "{%0,%1,%2,%3}, {%4,%5,%6,%7}, {%8,%9}, {%0,%1,%2,%3};"
        : "+f"(c[0]), "+f"(c[1]), "+f"(c[2]), "+f"(c[3])
        : "r"(a[0]), "r"(a[1]), "r"(a[2]), "r"(a[3]), "r"(b0), "r"(b1));
}

// ---------------------------------------------------------------------------
// Fused prepass: x -> A-frag fp16, W_qkv/W_out -> B-frag fp16.
// ---------------------------------------------------------------------------
__device__ __forceinline__ void perm_a_body(const float4* __restrict__ src,
                                            uint4* __restrict__ dst, int t) {
    int g = t & 7, c = (t >> 3) & 63, Mtile = t >> 9;
    int m0 = Mtile * 16 + g;
    float f0[16], f1[16];
#pragma unroll
    for (int j = 0; j < 4; j++) {
        float4 v0 = src[m0 * 256 + c * 4 + j];
        float4 v1 = src[(m0 + 8) * 256 + c * 4 + j];
        f0[4*j+0]=v0.x; f0[4*j+1]=v0.y; f0[4*j+2]=v0.z; f0[4*j+3]=v0.w;
        f1[4*j+0]=v1.x; f1[4*j+1]=v1.y; f1[4*j+2]=v1.z; f1[4*j+3]=v1.w;
    }
    int base = (Mtile * 64 + c) * 32 + g * 4;
#pragma unroll
    for (int tig = 0; tig < 4; tig++) {
        uint4 w;
        w.x = f2h2(f0[2*tig],   f0[2*tig+1]);
        w.y = f2h2(f1[2*tig],   f1[2*tig+1]);
        w.z = f2h2(f0[2*tig+8], f0[2*tig+9]);
        w.w = f2h2(f1[2*tig+8], f1[2*tig+9]);
        dst[base + tig] = w;
    }
}

__device__ __forceinline__ void perm_b_body(const float4* __restrict__ src,
                                            uint32_t* __restrict__ dst, int N, int t) {
    int Kblk = t & 127, Ntile = t >> 7;
    float w[8][8];
#pragma unroll
    for (int kk = 0; kk < 8; kk++) {
        int k = Kblk * 8 + kk;
        float4 wa = src[(size_t)k * (N / 4) + Ntile * 2];
        float4 wb = src[(size_t)k * (N / 4) + Ntile * 2 + 1];
        w[kk][0]=wa.x; w[kk][1]=wa.y; w[kk][2]=wa.z; w[kk][3]=wa.w;
        w[kk][4]=wb.x; w[kk][5]=wb.y; w[kk][6]=wb.z; w[kk][7]=wb.w;
    }
    int c = Kblk >> 1, kb = Kblk & 1;
    int base = (Ntile * 64 + c) * 64 + kb;
#pragma unroll
    for (int l = 0; l < 32; l++) {
        int g = l >> 2, tig = l & 3;
        dst[base + l * 2] = f2h2(w[2*tig][g], w[2*tig+1][g]);
    }
}

__global__ __launch_bounds__(256) void perm_all(const float4* __restrict__ x,
                                                const float4* __restrict__ wqkv,
                                                const float4* __restrict__ wout) {
    int b = blockIdx.x;
    if (b < 1024) {
        perm_a_body(x, (uint4*)g_xrw, b * 256 + threadIdx.x);
    } else if (b < 1216) {
        perm_b_body(wqkv, g_wqkvw, 3 * DMODEL, (b - 1024) * 256 + threadIdx.x);
    } else {
        perm_b_body(wout, g_woutw, DMODEL, (b - 1216) * 256 + threadIdx.x);
    }
}

// ---------------------------------------------------------------------------
// fp16 m16n8k16 GEMM, 3-stage cp.async pipeline. MODE 0 epilogue scatters
// q (flash A-frag), k (flash B-frag), and V directly in flash B-frag order
// (fused transpose via warp shuffles).
// ---------------------------------------------------------------------------
#define STAGE_BYTES 32768
#define GEMM_SMEM   (3 * STAGE_BYTES)      // 98304

template<int MODE>
__global__ __launch_bounds__(256) void gemm_f16(const float* __restrict__ bias,
                                                float* __restrict__ out, int Ntot) {
    extern __shared__ char smem[];
    const uint32_t sb = smem_u32(smem);
    const int tid  = threadIdx.x;
    const int lane = tid & 31;
    const int warp = tid >> 5;
    const int mw = warp & 1;
    const int nw = warp >> 1;
    const int g   = lane >> 2;
    const int tig = lane & 3;
    const int brow = blockIdx.y * 128;
    const int bcol = blockIdx.x * 128;
    const int Mtile0 = blockIdx.y * 8;
    const int Ntile0 = blockIdx.x * 16;

    const uint4* __restrict__ A4 = (const uint4*)(MODE ? g_aow : g_xrw);
    const uint4* __restrict__ B4 = (const uint4*)(MODE ? g_woutw : g_wqkvw);

    float acc[4][4][4];
#pragma unroll
    for (int i = 0; i < 4; i++)
#pragma unroll
        for (int j = 0; j < 4; j++)
#pragma unroll
            for (int q = 0; q < 4; q++) acc[i][j][q] = 0.f;

    auto issue = [&](int ic, int s) {
        const int Kc0 = ic * 4;
        const uint32_t As = sb + (uint32_t)s * STAGE_BYTES;
        const uint32_t Bs = As + 16384u;
#pragma unroll
        for (int r = 0; r < 4; r++) {
            int idx = tid + r * 256;
            int ml = idx >> 7, c = (idx >> 5) & 3, l = idx & 31;
            cp16(As + (uint32_t)idx * 16,
                 &A4[(size_t)((Mtile0 + ml) * 64 + Kc0 + c) * 32 + l]);
        }
#pragma unroll
        for (int r = 0; r < 4; r++) {
            int idx = tid + r * 256;
            int nl = idx >> 6, c = (idx >> 4) & 3, l = idx & 15;
            cp16(Bs + (uint32_t)idx * 16,
                 &B4[(size_t)((Ntile0 + nl) * 64 + Kc0 + c) * 16 + l]);
        }
    };

    issue(0, 0); CP_COMMIT();
    issue(1, 1); CP_COMMIT();

    for (int ic = 0; ic < 16; ic++) {
        if (ic + 1 < 16) { CP_WAIT1(); } else { CP_WAIT0(); }
        __syncthreads();

        const int s = ic % 3;
        const uint4* As4 = (const uint4*)(smem + (size_t)s * STAGE_BYTES);
        const uint2* Bs2 = (const uint2*)(smem + (size_t)s * STAGE_BYTES + 16384);

#pragma unroll
        for (int c = 0; c < 4; c++) {
            uint4 af[4];
            uint2 bf[4];
#pragma unroll
            for (int mt = 0; mt < 4; mt++)
                af[mt] = As4[((mw * 4 + mt) * 4 + c) * 32 + lane];
#pragma unroll
            for (int nt = 0; nt < 4; nt++)
                bf[nt] = Bs2[((nw * 4 + nt) * 4 + c) * 32 + lane];
#pragma unroll
            for (int mt = 0; mt < 4; mt++)
#pragma unroll
                for (int nt = 0; nt < 4; nt++)
                    mma_f16(acc[mt][nt], (const uint32_t*)&af[mt], bf[nt].x, bf[nt].y);
        }

        if (ic + 2 < 16) { issue(ic + 2, (ic + 2) % 3); CP_COMMIT(); }
    }

    // ----- epilogue -----
#pragma unroll
    for (int mt = 0; mt < 4; mt++) {
        const int m0r = brow + mw * 64 + mt * 16 + g;        // half 0 (t mod 16 = g)
        const int b0 = m0r >> 11, t0 = m0r & 2047;
#pragma unroll
        for (int nt = 0; nt < 4; nt++) {
            const int col = bcol + nw * 32 + nt * 8 + 2 * tig;
            float vx0 = acc[mt][nt][0] + bias[col];
            float vy0 = acc[mt][nt][1] + bias[col + 1];
            float vx1 = acc[mt][nt][2] + bias[col];
            float vy1 = acc[mt][nt][3] + bias[col + 1];
            if (MODE == 1) {
                *(float2*)&out[(size_t)m0r * DMODEL + col] = make_float2(vx0, vy0);
                *(float2*)&out[(size_t)(m0r + 8) * DMODEL + col] = make_float2(vx1, vy1);
                continue;
            }
            const int seg = col >> 10;
            const int dc  = col & 1023;
            const int h = dc >> 6, hd = dc & 63;
            const int bh = b0 * NHEAD + h;
            if (seg == 0) {          // q: flash A-frag order, pre-scaled
                uint32_t w0 = f2h2(vx0 * QSCALE, vy0 * QSCALE);
                uint32_t w1 = f2h2(vx1 * QSCALE, vy1 * QSCALE);
                int ibase = (((bh * 128 + (t0 >> 4)) * 4 + (hd >> 4)) * 32
                             + g * 4 + tig) * 4 + 2 * ((hd >> 3) & 1);
                g_qw[ibase]     = w0;
                g_qw[ibase + 1] = w1;
            } else if (seg == 1) {   // k: flash B-frag order
                uint32_t w0 = f2h2(vx0, vy0);
                uint32_t w1 = f2h2(vx1, vy1);
                int i0 = (((bh * 256 + (t0 >> 3)) * 4 + (hd >> 4)) * 32
                          + g * 4 + tig) * 2 + ((hd >> 3) & 1);
                int i1 = (((bh * 256 + ((t0 + 8) >> 3)) * 4 + (hd >> 4)) * 32
                          + g * 4 + tig) * 2 + ((hd >> 3) & 1);
                g_kw[i0] = w0;
                g_kw[i1] = w1;
            } else {                 // v: flash B-frag order via shuffles
                float px0 = __shfl_down_sync(0xffffffffu, vx0, 4);
                float py0 = __shfl_down_sync(0xffffffffu, vy0, 4);
                float px1 = __shfl_down_sync(0xffffffffu, vx1, 4);
                float py1 = __shfl_down_sync(0xffffffffu, vy1, 4);
                if ((g & 1) == 0) {
                    const int win = t0 >> 6, ksc = (t0 >> 4) & 3;
                    const int tv = g >> 1;
                    uint2 wa, wb;
                    wa.x = f2h2(vx0, px0); wa.y = f2h2(vx1, px1);
                    wb.x = f2h2(vy0, py0); wb.y = f2h2(vy1, py1);
                    uint2* dst = (uint2*)g_vt;
                    const int na = hd, nb = hd + 1;
                    dst[(size_t)(bh * 32 + win) * 1024
                        + ((na >> 3) * 4 + ksc) * 32 + (na & 7) * 4 + tv] = wa;
                    dst[(size_t)(bh * 32 + win) * 1024
                        + ((nb >> 3) * 4 + ksc) * 32 + (nb & 7) * 4 + tv] = wb;
                }
            }
        }
    }
}

// ---------------------------------------------------------------------------
// Flash attention, causal, fp16 m16n8k16.
// 8 warps x 32 q-rows = 256 q-rows per CTA (two m16 sub-tiles/warp):
// each K/V tile fill now feeds 256 q-rows -> KV traffic and barriers halve.
// 3-stage KV pipeline, one barrier per tile. 256 threads, 1 CTA/SM.
// ---------------------------------------------------------------------------
#define STAGE_W 4096                        // 2048 K words + 2048 V words
#define FLASH_SMEM (3 * STAGE_W * 4)        // 49152 B

__global__ __launch_bounds__(256, 1) void flash_attn_f16() {
    extern __shared__ uint32_t smw[];

    const int tid  = threadIdx.x;
    const int lane = tid & 31;
    const int warp = tid >> 5;               // 0..7
    const int g    = lane >> 2;
    const int tig  = lane & 3;
    const int qt = (int)gridDim.x - 1 - (int)blockIdx.x;   // 0..7, big first
    const int bh = blockIdx.y;
    const int q0 = qt * 256;

    // Q a-fragments for both sub-tiles (rows warp*32 .. warp*32+31)
    uint32_t aq[2][4][4];
#pragma unroll
    for (int sub = 0; sub < 2; sub++) {
        const int Mt = qt * 16 + warp * 2 + sub;
#pragma unroll
        for (int ksc = 0; ksc < 4; ksc++) {
            uint4 w = *(const uint4*)&g_qw[(((bh * 128 + Mt) * 4 + ksc) * 32 + lane) * 4];
            aq[sub][ksc][0] = w.x; aq[sub][ksc][1] = w.y;
            aq[sub][ksc][2] = w.z; aq[sub][ksc][3] = w.w;
        }
    }

    const int qrow_w = q0 + warp * 32;        // warp's first q row
    float mx[2][2], lv[2][2];
#pragma unroll
    for (int s2 = 0; s2 < 2; s2++) {
        mx[s2][0] = -1e30f; mx[s2][1] = -1e30f;
        lv[s2][0] = 0.f;    lv[s2][1] = 0.f;
    }
    float o[2][8][4];
#pragma unroll
    for (int sub = 0; sub < 2; sub++)
#pragma unroll
        for (int nt = 0; nt < 8; nt++)
#pragma unroll
            for (int q = 0; q < 4; q++) o[sub][nt][q] = 0.f;

    const uint32_t sb = smem_u32(smw);
    const int njt = 4 * qt + 4;
    const uint32_t ONES = 0x3C003C00u;

    auto issue_kv = [&](int jt, int s) {
        const uint32_t base = sb + (uint32_t)s * STAGE_W * 4;
        const uint4* srcK = (const uint4*)&g_kw[(size_t)(bh * 256 + jt * 8) * 256];
#pragma unroll
        for (int r = 0; r < 2; r++) {
            int idx = tid + r * 256;
            cp16(base + (uint32_t)idx * 16, &srcK[idx]);
        }
        const uint4* srcV = (const uint4*)&g_vt[(size_t)(bh * 32 + jt) * 2048];
#pragma unroll
        for (int r = 0; r < 2; r++) {
            int idx = tid + r * 256;
            cp16(base + 8192u + (uint32_t)idx * 16, &srcV[idx]);
        }
    };

    issue_kv(0, 0); CP_COMMIT();
    issue_kv(1, 1); CP_COMMIT();

    for (int jt = 0; jt < njt; jt++) {
        if (jt + 1 < njt) { CP_WAIT1(); } else { CP_WAIT0(); }
        __syncthreads();

        const int s = jt % 3;
        const int k0 = jt * 64;

        if (qrow_w + 31 >= k0) {
            const uint2* Kb = (const uint2*)(smw + (size_t)s * STAGE_W);
            const uint2* Vb = (const uint2*)(smw + (size_t)s * STAGE_W + 2048);

            // ----- S = Q @ K^T : one b-frag LDS feeds both sub-tiles -----
            float sc[2][8][4];
#pragma unroll
            for (int sub = 0; sub < 2; sub++)
#pragma unroll
                for (int nt = 0; nt < 8; nt++)
#pragma unroll
                    for (int q = 0; q < 4; q++) sc[sub][nt][q] = 0.f;
#pragma unroll
            for (int ksc = 0; ksc < 4; ksc++) {
#pragma unroll
                for (int nt = 0; nt < 8; nt++) {
                    uint2 bb = Kb[(nt * 4 + ksc) * 32 + lane];
                    mma_f16(sc[0][nt], aq[0][ksc], bb.x, bb.y);
                    mma_f16(sc[1][nt], aq[1][ksc], bb.x, bb.y);
                }
            }

            // ----- causal mask per sub-tile -----
#pragma unroll
            for (int sub = 0; sub < 2; sub++) {
                const int base_row = qrow_w + sub * 16;
                if (k0 + 63 > base_row) {
                    const int row0 = base_row + g, row1 = row0 + 8;
#pragma unroll
                    for (int nt = 0; nt < 8; nt++) {
                        const int col = k0 + nt * 8 + 2 * tig;
                        if (col     > row0) sc[sub][nt][0] = -1e30f;
                        if (col + 1 > row0) sc[sub][nt][1] = -1e30f;
                        if (col     > row1) sc[sub][nt][2] = -1e30f;
                        if (col + 1 > row1) sc[sub][nt][3] = -1e30f;
                    }
                }
            }

            // ----- online softmax per sub-tile (log2 domain) -----
            uint32_t pa[2][4][4];
#pragma unroll
            for (int sub = 0; sub < 2; sub++) {
                float rm0 = -1e30f, rm1 = -1e30f;
#pragma unroll
                for (int nt = 0; nt < 8; nt++) {
                    rm0 = fmaxf(rm0, fmaxf(sc[sub][nt][0], sc[sub][nt][1]));
                    rm1 = fmaxf(rm1, fmaxf(sc[sub][nt][2], sc[sub][nt][3]));
                }
                rm0 = fmaxf(rm0, __shfl_xor_sync(0xffffffffu, rm0, 1));
                rm0 = fmaxf(rm0, __shfl_xor_sync(0xffffffffu, rm0, 2));
                rm1 = fmaxf(rm1, __shfl_xor_sync(0xffffffffu, rm1, 1));
                rm1 = fmaxf(rm1, __shfl_xor_sync(0xffffffffu, rm1, 2));
                const float mn0 = fmaxf(mx[sub][0], rm0);
                const float mn1 = fmaxf(mx[sub][1], rm1);
                const float c0 = exp2f(mx[sub][0] - mn0);
                const float c1 = exp2f(mx[sub][1] - mn1);
#pragma unroll
                for (int nt = 0; nt < 8; nt++) {
                    pa[sub][nt >> 1][(nt & 1) * 2 + 0] =
                        h2exp2(sc[sub][nt][0] - mn0, sc[sub][nt][1] - mn0);
                    pa[sub][nt >> 1][(nt & 1) * 2 + 1] =
                        h2exp2(sc[sub][nt][2] - mn1, sc[sub][nt][3] - mn1);
                    o[sub][nt][0] *= c0; o[sub][nt][1] *= c0;
                    o[sub][nt][2] *= c1; o[sub][nt][3] *= c1;
                }
                float rsum[4] = {0.f, 0.f, 0.f, 0.f};
#pragma unroll
                for (int ksc = 0; ksc < 4; ksc++)
                    mma_f16(rsum, pa[sub][ksc], ONES, ONES);
                lv[sub][0] = lv[sub][0] * c0 + rsum[0]; mx[sub][0] = mn0;
                lv[sub][1] = lv[sub][1] * c1 + rsum[2]; mx[sub][1] = mn1;
            }

            // ----- O += P @ V : one b-frag LDS feeds both sub-tiles -----
#pragma unroll
            for (int ksc = 0; ksc < 4; ksc++) {
#pragma unroll
                for (int nt = 0; nt < 8; nt++) {
                    uint2 bb = Vb[(nt * 4 + ksc) * 32 + lane];
                    mma_f16(o[0][nt], pa[0][ksc], bb.x, bb.y);
                    mma_f16(o[1][nt], pa[1][ksc], bb.x, bb.y);
                }
            }
        }

        if (jt + 2 < njt) { issue_kv(jt + 2, (jt + 2) % 3); CP_COMMIT(); }
    }

    // ----- normalize + write g_aow in fp16 A-frag order -----
    const int b = bh >> 4;
    const int h = bh & 15;
#pragma unroll
    for (int sub = 0; sub < 2; sub++) {
        const float inv0 = 1.0f / lv[sub][0], inv1 = 1.0f / lv[sub][1];
        const int MtO = b * 128 + qt * 16 + warp * 2 + sub;
#pragma unroll
        for (int nt = 0; nt < 8; nt++) {
            const int chunk = h * 4 + (nt >> 1);
            const int base = ((MtO * 64 + chunk) * 32 + lane) * 4 + 2 * (nt & 1);
            g_aow[base]     = f2h2(o[sub][nt][0] * inv0, o[sub][nt][1] * inv0);
            g_aow[base + 1] = f2h2(o[sub][nt][2] * inv1, o[sub][nt][3] * inv1);
        }
    }
}

// ---------------------------------------------------------------------------
extern "C" void kernel_launch(void* const* d_in, const int* in_sizes, int n_in,
                              void* d_out, int out_size) {
    const float* x     = (const float*)d_in[0];
    const float* W_qkv = (const float*)d_in[1];
    const float* b_qkv = (const float*)d_in[2];
    const float* W_out = (const float*)d_in[3];
    const float* b_out = (const float*)d_in[4];
    float* out = (float*)d_out;

    cudaFuncSetAttribute(gemm_f16<0>, cudaFuncAttributeMaxDynamicSharedMemorySize, GEMM_SMEM);
    cudaFuncSetAttribute(gemm_f16<1>, cudaFuncAttributeMaxDynamicSharedMemorySize, GEMM_SMEM);
    cudaFuncSetAttribute(flash_attn_f16, cudaFuncAttributeMaxDynamicSharedMemorySize, FLASH_SMEM);

    perm_all<<<1280, 256>>>((const float4*)x, (const float4*)W_qkv, (const float4*)W_out);

    gemm_f16<0><<<dim3(3 * DMODEL / 128, MTOT / 128), 256, GEMM_SMEM>>>(b_qkv, nullptr, 3 * DMODEL);
    flash_attn_f16<<<dim3(TLEN / 256, BATCH * NHEAD), 256, FLASH_SMEM>>>();
    gemm_f16<1><<<dim3(DMODEL / 128, MTOT / 128), 256, GEMM_SMEM>>>(b_out, out, DMODEL);
}

// round 17
// speedup vs baseline: 1.0307x; 1.0307x over previous
#include <cuda_runtime.h>
#include <cuda_fp16.h>
#include <cstdint>
#include <math.h>

// Problem constants
#define DMODEL 1024
#define TLEN   2048
#define BATCH  4
#define NHEAD  16
#define HDIM   64
#define MTOT   (BATCH*TLEN)      // 8192

#define QSCALE (0.125f * 1.44269504089f)   // 1/sqrt(64) * log2(e), folded into q

// ---------------------------------------------------------------------------
// Global scratch, all fp16 stored as uint32 half2-words.
// ---------------------------------------------------------------------------
__device__ uint32_t g_qw  [4194304];   // flash A-frag order
__device__ uint32_t g_kw  [4194304];   // flash B-frag order
__device__ uint32_t g_vt  [4194304];   // flash B-frag order (per 64-row window)
__device__ uint32_t g_aow [4194304];   // GEMM A-frag order
__device__ uint32_t g_xrw [4194304];   // GEMM A-frag order
__device__ uint32_t g_wqkvw[1572864];  // GEMM B-frag order
__device__ uint32_t g_woutw[524288];

// ---------------------------------------------------------------------------
// Helpers
// ---------------------------------------------------------------------------
__device__ __forceinline__ uint32_t smem_u32(const void* p) {
    uint32_t a;
    asm("{ .reg .u64 t; cvta.to.shared.u64 t, %1; cvt.u32.u64 %0, t; }"
        : "=r"(a) : "l"(p));
    return a;
}

__device__ __forceinline__ uint32_t f2h2(float lo, float hi) {
    __half2 h = __floats2half2_rn(lo, hi);
    return *reinterpret_cast<uint32_t*>(&h);
}

__device__ __forceinline__ uint32_t h2exp2(float a, float b) {
    uint32_t h = f2h2(a, b), r;
    asm("ex2.approx.f16x2 %0, %1;" : "=r"(r) : "r"(h));
    return r;
}

__device__ __forceinline__ void cp16(uint32_t dst, const void* src) {
    asm volatile("cp.async.cg.shared.global [%0], [%1], 16;"
                 :: "r"(dst), "l"(src) : "memory");
}
#define CP_COMMIT() asm volatile("cp.async.commit_group;" ::: "memory")
#define CP_WAIT1()  asm volatile("cp.async.wait_group 1;" ::: "memory")
#define CP_WAIT0()  asm volatile("cp.async.wait_group 0;" ::: "memory")
#define CP_WAIT2()  asm volatile("cp.async.wait_group 2;" ::: "memory")

// m16n8k16 row.col fp16 MMA, fp32 accumulate
__device__ __forceinline__ void mma_f16(float* c, const uint32_t* a,
                                        uint32_t b0, uint32_t b1) {
    asm volatile(
        "mma.sync.aligned.m16n8k16.row.col.f32.f16.f16.f32 "
        "{%0,%1,%2,%3}, {%4,%5,%6,%7}, {%8,%9}, {%0,%1,%2,%3};"
        : "+f"(c[0]), "+f"(c[1]), "+f"(c[2]), "+f"(c[3])
        : "r"(a[0]), "r"(a[1]), "r"(a[2]), "r"(a[3]), "r"(b0), "r"(b1));
}

// ---------------------------------------------------------------------------
// Fused prepass: x -> A-frag fp16, W_qkv/W_out -> B-frag fp16.
// ---------------------------------------------------------------------------
__device__ __forceinline__ void perm_a_body(const float4* __restrict__ src,
                                            uint4* __restrict__ dst, int t) {
    int g = t & 7, c = (t >> 3) & 63, Mtile = t >> 9;
    int m0 = Mtile * 16 + g;
    float f0[16], f1[16];
#pragma unroll
    for (int j = 0; j < 4; j++) {
        float4 v0 = src[m0 * 256 + c * 4 + j];
        float4 v1 = src[(m0 + 8) * 256 + c * 4 + j];
        f0[4*j+0]=v0.x; f0[4*j+1]=v0.y; f0[4*j+2]=v0.z; f0[4*j+3]=v0.w;
        f1[4*j+0]=v1.x; f1[4*j+1]=v1.y; f1[4*j+2]=v1.z; f1[4*j+3]=v1.w;
    }
    int base = (Mtile * 64 + c) * 32 + g * 4;
#pragma unroll
    for (int tig = 0; tig < 4; tig++) {
        uint4 w;
        w.x = f2h2(f0[2*tig],   f0[2*tig+1]);
        w.y = f2h2(f1[2*tig],   f1[2*tig+1]);
        w.z = f2h2(f0[2*tig+8], f0[2*tig+9]);
        w.w = f2h2(f1[2*tig+8], f1[2*tig+9]);
        dst[base + tig] = w;
    }
}

__device__ __forceinline__ void perm_b_body(const float4* __restrict__ src,
                                            uint32_t* __restrict__ dst, int N, int t) {
    int Kblk = t & 127, Ntile = t >> 7;
    float w[8][8];
#pragma unroll
    for (int kk = 0; kk < 8; kk++) {
        int k = Kblk * 8 + kk;
        float4 wa = src[(size_t)k * (N / 4) + Ntile * 2];
        float4 wb = src[(size_t)k * (N / 4) + Ntile * 2 + 1];
        w[kk][0]=wa.x; w[kk][1]=wa.y; w[kk][2]=wa.z; w[kk][3]=wa.w;
        w[kk][4]=wb.x; w[kk][5]=wb.y; w[kk][6]=wb.z; w[kk][7]=wb.w;
    }
    int c = Kblk >> 1, kb = Kblk & 1;
    int base = (Ntile * 64 + c) * 64 + kb;
#pragma unroll
    for (int l = 0; l < 32; l++) {
        int g = l >> 2, tig = l & 3;
        dst[base + l * 2] = f2h2(w[2*tig][g], w[2*tig+1][g]);
    }
}

__global__ __launch_bounds__(256) void perm_all(const float4* __restrict__ x,
                                                const float4* __restrict__ wqkv,
                                                const float4* __restrict__ wout) {
    int b = blockIdx.x;
    if (b < 1024) {
        perm_a_body(x, (uint4*)g_xrw, b * 256 + threadIdx.x);
    } else if (b < 1216) {
        perm_b_body(wqkv, g_wqkvw, 3 * DMODEL, (b - 1024) * 256 + threadIdx.x);
    } else {
        perm_b_body(wout, g_woutw, DMODEL, (b - 1216) * 256 + threadIdx.x);
    }
}

// ---------------------------------------------------------------------------
// fp16 m16n8k16 GEMM, 3-stage cp.async pipeline; next-stage issue hoisted
// BEFORE compute for full load/compute overlap. MODE 0 epilogue scatters
// q (flash A-frag), k (flash B-frag), V (flash B-frag via shuffles).
// ---------------------------------------------------------------------------
#define STAGE_BYTES 32768
#define GEMM_SMEM   (3 * STAGE_BYTES)      // 98304

template<int MODE>
__global__ __launch_bounds__(256) void gemm_f16(const float* __restrict__ bias,
                                                float* __restrict__ out, int Ntot) {
    extern __shared__ char smem[];
    const uint32_t sb = smem_u32(smem);
    const int tid  = threadIdx.x;
    const int lane = tid & 31;
    const int warp = tid >> 5;
    const int mw = warp & 1;
    const int nw = warp >> 1;
    const int g   = lane >> 2;
    const int tig = lane & 3;
    const int brow = blockIdx.y * 128;
    const int bcol = blockIdx.x * 128;
    const int Mtile0 = blockIdx.y * 8;
    const int Ntile0 = blockIdx.x * 16;

    const uint4* __restrict__ A4 = (const uint4*)(MODE ? g_aow : g_xrw);
    const uint4* __restrict__ B4 = (const uint4*)(MODE ? g_woutw : g_wqkvw);

    float acc[4][4][4];
#pragma unroll
    for (int i = 0; i < 4; i++)
#pragma unroll
        for (int j = 0; j < 4; j++)
#pragma unroll
            for (int q = 0; q < 4; q++) acc[i][j][q] = 0.f;

    auto issue = [&](int ic, int s) {
        const int Kc0 = ic * 4;
        const uint32_t As = sb + (uint32_t)s * STAGE_BYTES;
        const uint32_t Bs = As + 16384u;
#pragma unroll
        for (int r = 0; r < 4; r++) {
            int idx = tid + r * 256;
            int ml = idx >> 7, c = (idx >> 5) & 3, l = idx & 31;
            cp16(As + (uint32_t)idx * 16,
                 &A4[(size_t)((Mtile0 + ml) * 64 + Kc0 + c) * 32 + l]);
        }
#pragma unroll
        for (int r = 0; r < 4; r++) {
            int idx = tid + r * 256;
            int nl = idx >> 6, c = (idx >> 4) & 3, l = idx & 15;
            cp16(Bs + (uint32_t)idx * 16,
                 &B4[(size_t)((Ntile0 + nl) * 64 + Kc0 + c) * 16 + l]);
        }
    };

    issue(0, 0); CP_COMMIT();
    issue(1, 1); CP_COMMIT();

    for (int ic = 0; ic < 16; ic++) {
        // wait until stage ic resident: groups in flight after issue-hoist can
        // be {ic (ready), ic+1, ic+2}; waiting for <=2 pending keeps ic ready.
        if (ic + 1 < 16) { CP_WAIT1(); } else { CP_WAIT0(); }
        __syncthreads();

        // hoisted prefetch of stage ic+2 (buffer (ic+2)%3 free by barrier)
        if (ic + 2 < 16) { issue(ic + 2, (ic + 2) % 3); CP_COMMIT(); }

        const int s = ic % 3;
        const uint4* As4 = (const uint4*)(smem + (size_t)s * STAGE_BYTES);
        const uint2* Bs2 = (const uint2*)(smem + (size_t)s * STAGE_BYTES + 16384);

#pragma unroll
        for (int c = 0; c < 4; c++) {
            uint4 af[4];
            uint2 bf[4];
#pragma unroll
            for (int mt = 0; mt < 4; mt++)
                af[mt] = As4[((mw * 4 + mt) * 4 + c) * 32 + lane];
#pragma unroll
            for (int nt = 0; nt < 4; nt++)
                bf[nt] = Bs2[((nw * 4 + nt) * 4 + c) * 32 + lane];
#pragma unroll
            for (int mt = 0; mt < 4; mt++)
#pragma unroll
                for (int nt = 0; nt < 4; nt++)
                    mma_f16(acc[mt][nt], (const uint32_t*)&af[mt], bf[nt].x, bf[nt].y);
        }
    }

    // ----- epilogue -----
#pragma unroll
    for (int mt = 0; mt < 4; mt++) {
        const int m0r = brow + mw * 64 + mt * 16 + g;        // half 0 (t mod 16 = g)
        const int b0 = m0r >> 11, t0 = m0r & 2047;
#pragma unroll
        for (int nt = 0; nt < 4; nt++) {
            const int col = bcol + nw * 32 + nt * 8 + 2 * tig;
            float vx0 = acc[mt][nt][0] + bias[col];
            float vy0 = acc[mt][nt][1] + bias[col + 1];
            float vx1 = acc[mt][nt][2] + bias[col];
            float vy1 = acc[mt][nt][3] + bias[col + 1];
            if (MODE == 1) {
                *(float2*)&out[(size_t)m0r * DMODEL + col] = make_float2(vx0, vy0);
                *(float2*)&out[(size_t)(m0r + 8) * DMODEL + col] = make_float2(vx1, vy1);
                continue;
            }
            const int seg = col >> 10;
            const int dc  = col & 1023;
            const int h = dc >> 6, hd = dc & 63;
            const int bh = b0 * NHEAD + h;
            if (seg == 0) {          // q: flash A-frag order, pre-scaled
                uint32_t w0 = f2h2(vx0 * QSCALE, vy0 * QSCALE);
                uint32_t w1 = f2h2(vx1 * QSCALE, vy1 * QSCALE);
                int ibase = (((bh * 128 + (t0 >> 4)) * 4 + (hd >> 4)) * 32
                             + g * 4 + tig) * 4 + 2 * ((hd >> 3) & 1);
                g_qw[ibase]     = w0;
                g_qw[ibase + 1] = w1;
            } else if (seg == 1) {   // k: flash B-frag order
                uint32_t w0 = f2h2(vx0, vy0);
                uint32_t w1 = f2h2(vx1, vy1);
                int i0 = (((bh * 256 + (t0 >> 3)) * 4 + (hd >> 4)) * 32
                          + g * 4 + tig) * 2 + ((hd >> 3) & 1);
                int i1 = (((bh * 256 + ((t0 + 8) >> 3)) * 4 + (hd >> 4)) * 32
                          + g * 4 + tig) * 2 + ((hd >> 3) & 1);
                g_kw[i0] = w0;
                g_kw[i1] = w1;
            } else {                 // v: flash B-frag order via shuffles
                float px0 = __shfl_down_sync(0xffffffffu, vx0, 4);
                float py0 = __shfl_down_sync(0xffffffffu, vy0, 4);
                float px1 = __shfl_down_sync(0xffffffffu, vx1, 4);
                float py1 = __shfl_down_sync(0xffffffffu, vy1, 4);
                if ((g & 1) == 0) {
                    const int win = t0 >> 6, ksc = (t0 >> 4) & 3;
                    const int tv = g >> 1;
                    uint2 wa, wb;
                    wa.x = f2h2(vx0, px0); wa.y = f2h2(vx1, px1);
                    wb.x = f2h2(vy0, py0); wb.y = f2h2(vy1, py1);
                    uint2* dst = (uint2*)g_vt;
                    const int na = hd, nb = hd + 1;
                    dst[(size_t)(bh * 32 + win) * 1024
                        + ((na >> 3) * 4 + ksc) * 32 + (na & 7) * 4 + tv] = wa;
                    dst[(size_t)(bh * 32 + win) * 1024
                        + ((nb >> 3) * 4 + ksc) * 32 + (nb & 7) * 4 + tv] = wb;
                }
            }
        }
    }
}

// ---------------------------------------------------------------------------
// Flash attention, causal, fp16 m16n8k16 (R15 config restored: 4 warps x
// 32 q-rows, 128 q-rows/CTA, 2 CTAs/SM). Next-tile issue hoisted before
// compute. 3-stage KV pipeline, one barrier per tile.
// ---------------------------------------------------------------------------
#define STAGE_W 4096                        // 2048 K words + 2048 V words
#define FLASH_SMEM (3 * STAGE_W * 4)        // 49152 B

__global__ __launch_bounds__(128, 2) void flash_attn_f16() {
    extern __shared__ uint32_t smw[];

    const int tid  = threadIdx.x;
    const int lane = tid & 31;
    const int warp = tid >> 5;               // 0..3
    const int g    = lane >> 2;
    const int tig  = lane & 3;
    const int qt = (int)gridDim.x - 1 - (int)blockIdx.x;
    const int bh = blockIdx.y;
    const int q0 = qt * 128;

    uint32_t aq[2][4][4];
#pragma unroll
    for (int sub = 0; sub < 2; sub++) {
        const int Mt = qt * 8 + warp * 2 + sub;
#pragma unroll
        for (int ksc = 0; ksc < 4; ksc++) {
            uint4 w = *(const uint4*)&g_qw[(((bh * 128 + Mt) * 4 + ksc) * 32 + lane) * 4];
            aq[sub][ksc][0] = w.x; aq[sub][ksc][1] = w.y;
            aq[sub][ksc][2] = w.z; aq[sub][ksc][3] = w.w;
        }
    }

    const int qrow_w = q0 + warp * 32;
    float mx[2][2], lv[2][2];
#pragma unroll
    for (int s2 = 0; s2 < 2; s2++) {
        mx[s2][0] = -1e30f; mx[s2][1] = -1e30f;
        lv[s2][0] = 0.f;    lv[s2][1] = 0.f;
    }
    float o[2][8][4];
#pragma unroll
    for (int sub = 0; sub < 2; sub++)
#pragma unroll
        for (int nt = 0; nt < 8; nt++)
#pragma unroll
            for (int q = 0; q < 4; q++) o[sub][nt][q] = 0.f;

    const uint32_t sb = smem_u32(smw);
    const int njt = 2 * qt + 2;
    const uint32_t ONES = 0x3C003C00u;

    auto issue_kv = [&](int jt, int s) {
        const uint32_t base = sb + (uint32_t)s * STAGE_W * 4;
        const uint4* srcK = (const uint4*)&g_kw[(size_t)(bh * 256 + jt * 8) * 256];
#pragma unroll
        for (int r = 0; r < 4; r++) {
            int idx = tid + r * 128;
            cp16(base + (uint32_t)idx * 16, &srcK[idx]);
        }
        const uint4* srcV = (const uint4*)&g_vt[(size_t)(bh * 32 + jt) * 2048];
#pragma unroll
        for (int r = 0; r < 4; r++) {
            int idx = tid + r * 128;
            cp16(base + 8192u + (uint32_t)idx * 16, &srcV[idx]);
        }
    };

    issue_kv(0, 0); CP_COMMIT();
    issue_kv(1, 1); CP_COMMIT();

    for (int jt = 0; jt < njt; jt++) {
        if (jt + 1 < njt) { CP_WAIT1(); } else { CP_WAIT0(); }
        __syncthreads();

        // hoisted prefetch of tile jt+2
        if (jt + 2 < njt) { issue_kv(jt + 2, (jt + 2) % 3); CP_COMMIT(); }

        const int s = jt % 3;
        const int k0 = jt * 64;

        if (qrow_w + 31 >= k0) {
            const uint2* Kb = (const uint2*)(smw + (size_t)s * STAGE_W);
            const uint2* Vb = (const uint2*)(smw + (size_t)s * STAGE_W + 2048);

            float sc[2][8][4];
#pragma unroll
            for (int sub = 0; sub < 2; sub++)
#pragma unroll
                for (int nt = 0; nt < 8; nt++)
#pragma unroll
                    for (int q = 0; q < 4; q++) sc[sub][nt][q] = 0.f;
#pragma unroll
            for (int ksc = 0; ksc < 4; ksc++) {
#pragma unroll
                for (int nt = 0; nt < 8; nt++) {
                    uint2 bb = Kb[(nt * 4 + ksc) * 32 + lane];
                    mma_f16(sc[0][nt], aq[0][ksc], bb.x, bb.y);
                    mma_f16(sc[1][nt], aq[1][ksc], bb.x, bb.y);
                }
            }

#pragma unroll
            for (int sub = 0; sub < 2; sub++) {
                const int base_row = qrow_w + sub * 16;
                if (k0 + 63 > base_row) {
                    const int row0 = base_row + g, row1 = row0 + 8;
#pragma unroll
                    for (int nt = 0; nt < 8; nt++) {
                        const int col = k0 + nt * 8 + 2 * tig;
                        if (col     > row0) sc[sub][nt][0] = -1e30f;
                        if (col + 1 > row0) sc[sub][nt][1] = -1e30f;
                        if (col     > row1) sc[sub][nt][2] = -1e30f;
                        if (col + 1 > row1) sc[sub][nt][3] = -1e30f;
                    }
                }
            }

            uint32_t pa[2][4][4];
#pragma unroll
            for (int sub = 0; sub < 2; sub++) {
                float rm0 = -1e30f, rm1 = -1e30f;
#pragma unroll
                for (int nt = 0; nt < 8; nt++) {
                    rm0 = fmaxf(rm0, fmaxf(sc[sub][nt][0], sc[sub][nt][1]));
                    rm1 = fmaxf(rm1, fmaxf(sc[sub][nt][2], sc[sub][nt][3]));
                }
                rm0 = fmaxf(rm0, __shfl_xor_sync(0xffffffffu, rm0, 1));
                rm0 = fmaxf(rm0, __shfl_xor_sync(0xffffffffu, rm0, 2));
                rm1 = fmaxf(rm1, __shfl_xor_sync(0xffffffffu, rm1, 1));
                rm1 = fmaxf(rm1, __shfl_xor_sync(0xffffffffu, rm1, 2));
                const float mn0 = fmaxf(mx[sub][0], rm0);
                const float mn1 = fmaxf(mx[sub][1], rm1);
                const float c0 = exp2f(mx[sub][0] - mn0);
                const float c1 = exp2f(mx[sub][1] - mn1);
#pragma unroll
                for (int nt = 0; nt < 8; nt++) {
                    pa[sub][nt >> 1][(nt & 1) * 2 + 0] =
                        h2exp2(sc[sub][nt][0] - mn0, sc[sub][nt][1] - mn0);
                    pa[sub][nt >> 1][(nt & 1) * 2 + 1] =
                        h2exp2(sc[sub][nt][2] - mn1, sc[sub][nt][3] - mn1);
                    o[sub][nt][0] *= c0; o[sub][nt][1] *= c0;
                    o[sub][nt][2] *= c1; o[sub][nt][3] *= c1;
                }
                float rsum[4] = {0.f, 0.f, 0.f, 0.f};
#pragma unroll
                for (int ksc = 0; ksc < 4; ksc++)
                    mma_f16(rsum, pa[sub][ksc], ONES, ONES);
                lv[sub][0] = lv[sub][0] * c0 + rsum[0]; mx[sub][0] = mn0;
                lv[sub][1] = lv[sub][1] * c1 + rsum[2]; mx[sub][1] = mn1;
            }

#pragma unroll
            for (int ksc = 0; ksc < 4; ksc++) {
#pragma unroll
                for (int nt = 0; nt < 8; nt++) {
                    uint2 bb = Vb[(nt * 4 + ksc) * 32 + lane];
                    mma_f16(o[0][nt], pa[0][ksc], bb.x, bb.y);
                    mma_f16(o[1][nt], pa[1][ksc], bb.x, bb.y);
                }
            }
        }
    }

    const int b = bh >> 4;
    const int h = bh & 15;
#pragma unroll
    for (int sub = 0; sub < 2; sub++) {
        const float inv0 = 1.0f / lv[sub][0], inv1 = 1.0f / lv[sub][1];
        const int MtO = b * 128 + qt * 8 + warp * 2 + sub;
#pragma unroll
        for (int nt = 0; nt < 8; nt++) {
            const int chunk = h * 4 + (nt >> 1);
            const int base = ((MtO * 64 + chunk) * 32 + lane) * 4 + 2 * (nt & 1);
            g_aow[base]     = f2h2(o[sub][nt][0] * inv0, o[sub][nt][1] * inv0);
            g_aow[base + 1] = f2h2(o[sub][nt][2] * inv1, o[sub][nt][3] * inv1);
        }
    }
}

// ---------------------------------------------------------------------------
extern "C" void kernel_launch(void* const* d_in, const int* in_sizes, int n_in,
                              void* d_out, int out_size) {
    const float* x     = (const float*)d_in[0];
    const float* W_qkv = (const float*)d_in[1];
    const float* b_qkv = (const float*)d_in[2];
    const float* W_out = (const float*)d_in[3];
    const float* b_out = (const float*)d_in[4];
    float* out = (float*)d_out;

    cudaFuncSetAttribute(gemm_f16<0>, cudaFuncAttributeMaxDynamicSharedMemorySize, GEMM_SMEM);
    cudaFuncSetAttribute(gemm_f16<1>, cudaFuncAttributeMaxDynamicSharedMemorySize, GEMM_SMEM);
    cudaFuncSetAttribute(flash_attn_f16, cudaFuncAttributeMaxDynamicSharedMemorySize, FLASH_SMEM);

    perm_all<<<1280, 256>>>((const float4*)x, (const float4*)W_qkv, (const float4*)W_out);

    gemm_f16<0><<<dim3(3 * DMODEL / 128, MTOT / 128), 256, GEMM_SMEM>>>(b_qkv, nullptr, 3 * DMODEL);
    flash_attn_f16<<<dim3(TLEN / 128, BATCH * NHEAD), 128, FLASH_SMEM>>>();
    gemm_f16<1><<<dim3(DMODEL / 128, MTOT / 128), 256, GEMM_SMEM>>>(b_out, out, DMODEL);
}